// round 3
// baseline (speedup 1.0000x reference)
#include <cuda_runtime.h>
#include <cuda_bf16.h>
#include <math.h>

// ---------------- Problem constants ----------------
#define NN   512
#define LHIST 20
#define PLEN 10
#define HD   128      // H
#define ED   64       // E
#define NHEAD 10
#define FFD  2048
#define DD   130      // D = H+2
#define DHD  13       // D / NH
#define NLAY 3

// ---------------- Device state (no allocs allowed) ----------------
__device__ float g_Wcomb[4*HD*4];       // 512 x 4 fused (W_ih @ W_emb)
__device__ float g_bcomb[4*HD];         // fused gate bias
__device__ float g_x[NN*DD];            // transformer activations
__device__ float g_Sh[NN*HD];
__device__ float g_c[NN*HD];
__device__ float g_qkv[NN*3*DD];
__device__ float g_att[NN*DD];
__device__ float g_tmp[NN*DD];
__device__ float g_ff1[NN*FFD];
__device__ float g_part[8*NN*DD];       // split-K partials
__device__ float g_mlp1[NN*HD];
__device__ float g_mlp2[NN*HD];
__device__ float g_inp[NN*4];           // rollout feedback input

// ---------------- Setup: fold embedding into LSTM input weights ----------------
__global__ void k_setup(const float* __restrict__ W_ih, const float* __restrict__ W_emb,
                        const float* __restrict__ b_emb, const float* __restrict__ b_ih,
                        const float* __restrict__ b_hh) {
    int j = threadIdx.x;                // 0..511
    float wc0=0.f, wc1=0.f, wc2=0.f, wc3=0.f;
    float bb = b_ih[j] + b_hh[j];
    #pragma unroll 8
    for (int e = 0; e < ED; e++) {
        float w = W_ih[j*ED + e];
        bb  += w * b_emb[e];
        wc0 += w * W_emb[e*4 + 0];
        wc1 += w * W_emb[e*4 + 1];
        wc2 += w * W_emb[e*4 + 2];
        wc3 += w * W_emb[e*4 + 3];
    }
    g_Wcomb[j*4+0]=wc0; g_Wcomb[j*4+1]=wc1; g_Wcomb[j*4+2]=wc2; g_Wcomb[j*4+3]=wc3;
    g_bcomb[j]=bb;
}

__global__ void k_zero_state() {
    int i = blockIdx.x*blockDim.x + threadIdx.x;
    if (i < NN*HD) { g_Sh[i] = 0.f; g_c[i] = 0.f; }
}

// ---------------- Fused LSTM step: writes x = concat(h2, pos) ----------------
__device__ __forceinline__ float sigm(float x){ return 1.f/(1.f+expf(-x)); }

__global__ void k_lstm(const float* __restrict__ W_hh,
                       const float* __restrict__ inp_base, int inp_stride) {
    __shared__ float sSh[8][HD];
    __shared__ float sIn[8][4];
    int r0 = blockIdx.x * 8;            // 64 blocks x 8 rows
    int j  = threadIdx.x;               // 128 threads
    #pragma unroll
    for (int i = 0; i < 8; i++) sSh[i][j] = g_Sh[(r0+i)*HD + j];
    if (j < 32) {
        int r = j >> 2, f = j & 3;
        sIn[r][f] = inp_base[(r0+r)*inp_stride + f];
    }
    __syncthreads();
    float acc[4][8];
    #pragma unroll
    for (int gi = 0; gi < 4; gi++) {
        int row = gi*HD + j;
        float bb = g_bcomb[row];
        float a0=bb,a1=bb,a2=bb,a3=bb,a4=bb,a5=bb,a6=bb,a7=bb;
        #pragma unroll
        for (int f = 0; f < 4; f++) {
            float wc = g_Wcomb[row*4+f];
            a0+=wc*sIn[0][f]; a1+=wc*sIn[1][f]; a2+=wc*sIn[2][f]; a3+=wc*sIn[3][f];
            a4+=wc*sIn[4][f]; a5+=wc*sIn[5][f]; a6+=wc*sIn[6][f]; a7+=wc*sIn[7][f];
        }
        const float* wr = W_hh + row*HD;
        #pragma unroll 4
        for (int kk = 0; kk < HD; kk++) {
            float w = wr[kk];
            a0+=w*sSh[0][kk]; a1+=w*sSh[1][kk]; a2+=w*sSh[2][kk]; a3+=w*sSh[3][kk];
            a4+=w*sSh[4][kk]; a5+=w*sSh[5][kk]; a6+=w*sSh[6][kk]; a7+=w*sSh[7][kk];
        }
        acc[gi][0]=a0; acc[gi][1]=a1; acc[gi][2]=a2; acc[gi][3]=a3;
        acc[gi][4]=a4; acc[gi][5]=a5; acc[gi][6]=a6; acc[gi][7]=a7;
    }
    #pragma unroll
    for (int r = 0; r < 8; r++) {
        int n = r0 + r;
        float ig = acc[0][r], fg = acc[1][r], gg = acc[2][r], og = acc[3][r];
        float c2 = sigm(fg)*g_c[n*HD+j] + sigm(ig)*tanhf(gg);
        g_c[n*HD+j] = c2;
        g_x[n*DD + j] = sigm(og)*tanhf(c2);
        if (j < 2) g_x[n*DD + HD + j] = sIn[r][j];
    }
}

// ---------------- Generic tiled GEMM: C = A(MxK) @ B(NxK)^T [+bias][relu][+resid] ----------------
// flags: 1 = relu, 2 = add resid after relu. Split-K via gridDim.z (writes partials, no bias).
#define BM 64
#define BN 64
#define BKK 16
__global__ void k_gemm(const float* __restrict__ A, const float* __restrict__ B,
                       const float* __restrict__ bias, const float* __restrict__ resid,
                       float* __restrict__ C, int M, int N, int K, int kLen, int flags) {
    __shared__ float As[BKK][BM];
    __shared__ float Bs[BKK][BN+1];
    int tid = threadIdx.x;
    int tx = tid & 15, ty = tid >> 4;
    int bm = blockIdx.y * BM, bn = blockIdx.x * BN;
    int kStart = blockIdx.z * kLen;
    int kEnd = min(K, kStart + kLen);
    float acc[4][4] = {};
    for (int k0 = kStart; k0 < kEnd; k0 += BKK) {
        #pragma unroll
        for (int i = 0; i < 4; i++) {
            int e = tid + i*256;
            int m = e >> 4, kk = e & 15;
            int gm = bm + m, gk = k0 + kk;
            As[kk][m] = (gm < M && gk < kEnd) ? A[gm*K + gk] : 0.f;
        }
        #pragma unroll
        for (int i = 0; i < 4; i++) {
            int e = tid + i*256;
            int n = e >> 4, kk = e & 15;
            int gn = bn + n, gk = k0 + kk;
            Bs[kk][n] = (gn < N && gk < kEnd) ? B[gn*K + gk] : 0.f;
        }
        __syncthreads();
        #pragma unroll
        for (int kk = 0; kk < BKK; kk++) {
            float a[4], b[4];
            #pragma unroll
            for (int i = 0; i < 4; i++) a[i] = As[kk][ty*4+i];
            #pragma unroll
            for (int jj = 0; jj < 4; jj++) b[jj] = Bs[kk][tx*4+jj];
            #pragma unroll
            for (int i = 0; i < 4; i++)
                #pragma unroll
                for (int jj = 0; jj < 4; jj++) acc[i][jj] += a[i]*b[jj];
        }
        __syncthreads();
    }
    long zoff = (gridDim.z > 1) ? (long)blockIdx.z * M * N : 0;
    #pragma unroll
    for (int i = 0; i < 4; i++) {
        int m = bm + ty*4 + i;
        if (m >= M) continue;
        #pragma unroll
        for (int jj = 0; jj < 4; jj++) {
            int n = bn + tx*4 + jj;
            if (n >= N) continue;
            float v = acc[i][jj];
            if (bias)      v += bias[n];
            if (flags & 1) v = fmaxf(v, 0.f);
            if (flags & 2) v += resid[m*N + n];
            C[zoff + (long)m*N + n] = v;
        }
    }
}

// ---------------- Attention: one pass, K/V resident in smem (per head) ----------------
__global__ void k_attn(const float* __restrict__ qkv, float* __restrict__ att) {
    extern __shared__ float sm[];        // K: 512*13, V: 512*13
    float* sK = sm;
    float* sV = sm + NN*DHD;
    int h = blockIdx.x;
    int base_q = h*DHD, base_k = DD + h*DHD, base_v = 2*DD + h*DHD;
    for (int idx = threadIdx.x; idx < NN*DHD; idx += 64) {
        int r = idx / DHD, c = idx - r*DHD;
        sK[idx] = qkv[r*3*DD + base_k + c];
        sV[idx] = qkv[r*3*DD + base_v + c];
    }
    __syncthreads();
    int n = blockIdx.y * 64 + threadIdx.x;
    const float scale = rsqrtf((float)DHD);
    float q[DHD];
    #pragma unroll
    for (int c = 0; c < DHD; c++) q[c] = qkv[n*3*DD + base_q + c] * scale;
    float mx = -1e30f, l = 0.f, acc[DHD];
    #pragma unroll
    for (int c = 0; c < DHD; c++) acc[c] = 0.f;
    for (int m = 0; m < NN; m++) {
        float s = 0.f;
        #pragma unroll
        for (int c = 0; c < DHD; c++) s += q[c]*sK[m*DHD+c];
        float nm = fmaxf(mx, s);
        float corr = __expf(mx - nm);
        float p = __expf(s - nm);
        l = l*corr + p;
        #pragma unroll
        for (int c = 0; c < DHD; c++) acc[c] = acc[c]*corr + p*sV[m*DHD+c];
        mx = nm;
    }
    float rl = 1.f / l;
    #pragma unroll
    for (int c = 0; c < DHD; c++) att[n*DD + base_q + c] = acc[c]*rl;
}

// ---------------- Add (+partials,+bias) then LayerNorm in place on g_x-like buffer ----------------
__global__ void k_ln(float* __restrict__ x, const float* __restrict__ add, int P, int PS,
                     const float* __restrict__ bias,
                     const float* __restrict__ s, const float* __restrict__ b) {
    __shared__ float red1[8], red2[8];
    int row = blockIdx.x, tid = threadIdx.x;
    bool valid = tid < DD;
    float v = 0.f;
    if (valid) {
        v = x[row*DD + tid];
        if (bias) v += bias[tid];
        for (int p = 0; p < P; p++) v += add[(long)p*PS + row*DD + tid];
    }
    float s1 = v, s2 = v*v;
    #pragma unroll
    for (int o = 16; o; o >>= 1) {
        s1 += __shfl_down_sync(0xffffffffu, s1, o);
        s2 += __shfl_down_sync(0xffffffffu, s2, o);
    }
    if ((tid & 31) == 0) { red1[tid>>5] = s1; red2[tid>>5] = s2; }
    __syncthreads();
    if (tid < 8) {
        s1 = red1[tid]; s2 = red2[tid];
        #pragma unroll
        for (int o = 4; o; o >>= 1) {
            s1 += __shfl_down_sync(0xffu, s1, o);
            s2 += __shfl_down_sync(0xffu, s2, o);
        }
        if (tid == 0) { red1[0] = s1; red2[0] = s2; }
    }
    __syncthreads();
    float mean = red1[0] * (1.f/DD);
    float var  = red2[0] * (1.f/DD) - mean*mean;
    float rstd = rsqrtf(var + 1e-5f);
    if (valid) x[row*DD + tid] = (v - mean)*rstd*s[tid] + b[tid];
}

// ---------------- Rollout head: a = x@W_pl^T + b_pl; kinematics; write out + feedback ----------------
__global__ void k_head(const float* __restrict__ mlp2, const float* __restrict__ W_pl,
                       const float* __restrict__ b_pl,
                       const float* __restrict__ cf, int cfStride,
                       float* __restrict__ outp) {
    int n = blockIdx.x*blockDim.x + threadIdx.x;
    if (n >= NN) return;
    const float* xr = mlp2 + n*HD;
    float a0 = b_pl[0], a1 = b_pl[1];
    #pragma unroll 4
    for (int k = 0; k < HD; k++) {
        a0 += xr[k]*W_pl[k];
        a1 += xr[k]*W_pl[HD+k];
    }
    const float* c = cf + n*cfStride;
    const float DT = 0.1f;
    float v0 = a0*DT + c[2], v1 = a1*DT + c[3];
    float p0 = a0*(DT*DT*0.5f) + v0*DT + c[0];
    float p1 = a1*(DT*DT*0.5f) + v1*DT + c[1];
    outp[n*(PLEN*4)+0] = p0; outp[n*(PLEN*4)+1] = p1;
    outp[n*(PLEN*4)+2] = v0; outp[n*(PLEN*4)+3] = v1;
    g_inp[n*4+0] = p0; g_inp[n*4+1] = p1; g_inp[n*4+2] = v0; g_inp[n*4+3] = v1;
}

// ---------------- Host orchestration ----------------
extern "C" void kernel_launch(void* const* d_in, const int* in_sizes, int n_in,
                              void* d_out, int out_size) {
    const float* Tracks = (const float*)d_in[0];
    const float* W_emb  = (const float*)d_in[1];
    const float* b_emb  = (const float*)d_in[2];
    const float* W_ih   = (const float*)d_in[3];
    const float* W_hh   = (const float*)d_in[4];
    const float* b_ih   = (const float*)d_in[5];
    const float* b_hh   = (const float*)d_in[6];
    const float* qkv_w  = (const float*)d_in[7];
    const float* qkv_b  = (const float*)d_in[8];
    const float* out_w  = (const float*)d_in[9];
    const float* out_b  = (const float*)d_in[10];
    const float* ff1_w  = (const float*)d_in[11];
    const float* ff1_b  = (const float*)d_in[12];
    const float* ff2_w  = (const float*)d_in[13];
    const float* ff2_b  = (const float*)d_in[14];
    const float* ln1_s  = (const float*)d_in[15];
    const float* ln1_b  = (const float*)d_in[16];
    const float* ln2_s  = (const float*)d_in[17];
    const float* ln2_b  = (const float*)d_in[18];
    const float* W_sp   = (const float*)d_in[19];
    const float* b_sp   = (const float*)d_in[20];
    const float* W_p1   = (const float*)d_in[21];
    const float* b_p1   = (const float*)d_in[22];
    const float* W_p2   = (const float*)d_in[23];
    const float* b_p2   = (const float*)d_in[24];
    const float* W_pl   = (const float*)d_in[25];
    const float* b_pl   = (const float*)d_in[26];
    float* out = (float*)d_out;

    static const int ATTN_SMEM = 2*NN*DHD*(int)sizeof(float);  // 53248
    cudaFuncSetAttribute(k_attn, cudaFuncAttributeMaxDynamicSharedMemorySize, 56*1024);

    float *xp, *qkvp, *attp, *tmpp, *ff1p, *partp, *Shp, *m1p, *m2p, *inpp;
    cudaGetSymbolAddress((void**)&xp,    g_x);
    cudaGetSymbolAddress((void**)&qkvp,  g_qkv);
    cudaGetSymbolAddress((void**)&attp,  g_att);
    cudaGetSymbolAddress((void**)&tmpp,  g_tmp);
    cudaGetSymbolAddress((void**)&ff1p,  g_ff1);
    cudaGetSymbolAddress((void**)&partp, g_part);
    cudaGetSymbolAddress((void**)&Shp,   g_Sh);
    cudaGetSymbolAddress((void**)&m1p,   g_mlp1);
    cudaGetSymbolAddress((void**)&m2p,   g_mlp2);
    cudaGetSymbolAddress((void**)&inpp,  g_inp);

    auto gemm = [&](const float* A, const float* B, const float* bias, const float* resid,
                    float* C, int M, int Nn, int K, int splitK, int flags) {
        dim3 grid((Nn + BN - 1)/BN, (M + BM - 1)/BM, splitK);
        int kLen = (K + splitK - 1)/splitK;
        k_gemm<<<grid, 256>>>(A, B, bias, resid, C, M, Nn, K, kLen, flags);
    };

    auto sp = [&]() {
        for (int j = 0; j < NLAY; j++) {
            gemm(xp, qkv_w + (size_t)j*3*DD*DD, qkv_b + j*3*DD, nullptr, qkvp, NN, 3*DD, DD, 1, 0);
            k_attn<<<dim3(NHEAD, NN/64), 64, ATTN_SMEM>>>(qkvp, attp);
            gemm(attp, out_w + (size_t)j*DD*DD, out_b + j*DD, nullptr, tmpp, NN, DD, DD, 1, 0);
            k_ln<<<NN, 256>>>(xp, tmpp, 1, 0, nullptr, ln1_s + j*DD, ln1_b + j*DD);
            gemm(xp, ff1_w + (size_t)j*FFD*DD, ff1_b + j*FFD, nullptr, ff1p, NN, FFD, DD, 1, 1);
            gemm(ff1p, ff2_w + (size_t)j*DD*FFD, nullptr, nullptr, partp, NN, DD, FFD, 8, 0);
            k_ln<<<NN, 256>>>(xp, partp, 8, NN*DD, ff2_b + j*DD, ln2_s + j*DD, ln2_b + j*DD);
        }
        gemm(xp, W_sp, b_sp, nullptr, Shp, NN, HD, DD, 1, 0);
    };

    k_setup<<<1, 4*HD>>>(W_ih, W_emb, b_emb, b_ih, b_hh);
    k_zero_state<<<(NN*HD + 255)/256, 256>>>();

    // initial step (Sh=c=0), input Tracks[:,0,1:]
    k_lstm<<<NN/8, HD>>>(W_hh, Tracks + 1, LHIST*5);
    sp();
    // history scan
    for (int t = 0; t < LHIST; t++) {
        k_lstm<<<NN/8, HD>>>(W_hh, Tracks + t*5 + 1, LHIST*5);
        sp();
    }
    // rollout
    for (int t = 0; t < PLEN; t++) {
        gemm(Shp, W_p1, b_p1, Shp, m1p, NN, HD, HD, 1, 3);
        gemm(m1p, W_p2, b_p2, m1p, m2p, NN, HD, HD, 1, 3);
        const float* cf = (t == 0) ? (Tracks + (LHIST-1)*5 + 1) : inpp;
        int cfs = (t == 0) ? LHIST*5 : 4;
        k_head<<<2, 256>>>(m2p, W_pl, b_pl, cf, cfs, out + t*4);
        if (t < PLEN - 1) {          // last rm_sp's carry is discarded by the scan
            k_lstm<<<NN/8, HD>>>(W_hh, inpp, 4);
            sp();
        }
    }
}

// round 4
// speedup vs baseline: 1.0298x; 1.0298x over previous
#include <cuda_runtime.h>
#include <cuda_bf16.h>
#include <math.h>

// ---------------- Problem constants ----------------
#define NN   512
#define LHIST 20
#define PLEN 10
#define HD   128      // H
#define ED   64       // E
#define NHEAD 10
#define FFD  2048
#define DD   130      // D = H+2
#define DP   144      // padded D (multiple of 16)
#define DHD  13       // D / NH
#define NLAY 3

// ---------------- Device state (no allocs allowed) ----------------
__device__ float g_Wcomb[4*HD*4];
__device__ float g_bcomb[4*HD];
__device__ float g_x[NN*DP];            // transformer activations (padded)
__device__ float g_Sh[NN*HD];
__device__ float g_c[NN*HD];
__device__ float g_qkv[NN*3*DD];
__device__ float g_att[NN*DP];
__device__ float g_tmp[NN*DP];
__device__ float g_ff1[NN*FFD];
__device__ float g_part[8*NN*DP];       // split-K partials
__device__ float g_mlp1[NN*HD];
__device__ float g_mlp2[NN*HD];
__device__ float g_inp[NN*4];

// Repacked weights: K padded 130 -> 144
__device__ float g_qkvP[NLAY*3*DD*DP];  // 1170 x 144
__device__ float g_outP[NLAY*DD*DP];    // 390 x 144
__device__ float g_ff1P[NLAY*FFD*DP];   // 6144 x 144
__device__ float g_spP[HD*DP];          // 128 x 144

// ---------------- Setup: fold embedding into LSTM input weights ----------------
__global__ void k_setup(const float* __restrict__ W_ih, const float* __restrict__ W_emb,
                        const float* __restrict__ b_emb, const float* __restrict__ b_ih,
                        const float* __restrict__ b_hh) {
    int j = threadIdx.x;                // 0..511
    float wc0=0.f, wc1=0.f, wc2=0.f, wc3=0.f;
    float bb = b_ih[j] + b_hh[j];
    #pragma unroll 8
    for (int e = 0; e < ED; e++) {
        float w = W_ih[j*ED + e];
        bb  += w * b_emb[e];
        wc0 += w * W_emb[e*4 + 0];
        wc1 += w * W_emb[e*4 + 1];
        wc2 += w * W_emb[e*4 + 2];
        wc3 += w * W_emb[e*4 + 3];
    }
    g_Wcomb[j*4+0]=wc0; g_Wcomb[j*4+1]=wc1; g_Wcomb[j*4+2]=wc2; g_Wcomb[j*4+3]=wc3;
    g_bcomb[j]=bb;
}

// Zero state + pads of x/att
__global__ void k_init() {
    int i = blockIdx.x*blockDim.x + threadIdx.x;
    if (i < NN*HD) { g_Sh[i] = 0.f; g_c[i] = 0.f; }
    if (i < NN*DP) { g_x[i] = 0.f; g_att[i] = 0.f; }
}

// Repack K=130 weights to K=144 (zero padded)
#define RP_ROWS (NLAY*3*DD + NLAY*DD + NLAY*FFD + HD)   // 1170+390+6144+128 = 7832
__global__ void k_repack(const float* __restrict__ qkv_w, const float* __restrict__ out_w,
                         const float* __restrict__ ff1_w, const float* __restrict__ W_sp) {
    int idx = blockIdx.x*blockDim.x + threadIdx.x;
    if (idx >= RP_ROWS*DP) return;
    int row = idx / DP, k = idx - row*DP;
    const float* src; float* dst; int r;
    if (row < NLAY*3*DD)            { src = qkv_w; dst = g_qkvP; r = row; }
    else if (row < NLAY*3*DD+NLAY*DD){ src = out_w; dst = g_outP; r = row - NLAY*3*DD; }
    else if (row < NLAY*3*DD+NLAY*DD+NLAY*FFD) { src = ff1_w; dst = g_ff1P; r = row - NLAY*3*DD - NLAY*DD; }
    else                            { src = W_sp;  dst = g_spP;  r = row - NLAY*3*DD - NLAY*DD - NLAY*FFD; }
    dst[r*DP + k] = (k < DD) ? src[r*DD + k] : 0.f;
}

// ---------------- Fused LSTM step: writes x = concat(h2, pos) ----------------
__device__ __forceinline__ float sigm(float x){ return 1.f/(1.f+expf(-x)); }

__global__ void k_lstm(const float* __restrict__ W_hh,
                       const float* __restrict__ inp_base, int inp_stride) {
    __shared__ float sSh[8][HD];
    __shared__ float sIn[8][4];
    int r0 = blockIdx.x * 8;            // 64 blocks x 8 rows
    int j  = threadIdx.x;               // 128 threads
    #pragma unroll
    for (int i = 0; i < 8; i++) sSh[i][j] = g_Sh[(r0+i)*HD + j];
    if (j < 32) {
        int r = j >> 2, f = j & 3;
        sIn[r][f] = inp_base[(r0+r)*inp_stride + f];
    }
    __syncthreads();
    float acc[4][8];
    #pragma unroll
    for (int gi = 0; gi < 4; gi++) {
        int row = gi*HD + j;
        float bb = g_bcomb[row];
        float a0=bb,a1=bb,a2=bb,a3=bb,a4=bb,a5=bb,a6=bb,a7=bb;
        #pragma unroll
        for (int f = 0; f < 4; f++) {
            float wc = g_Wcomb[row*4+f];
            a0+=wc*sIn[0][f]; a1+=wc*sIn[1][f]; a2+=wc*sIn[2][f]; a3+=wc*sIn[3][f];
            a4+=wc*sIn[4][f]; a5+=wc*sIn[5][f]; a6+=wc*sIn[6][f]; a7+=wc*sIn[7][f];
        }
        const float* wr = W_hh + row*HD;
        #pragma unroll 4
        for (int kk = 0; kk < HD; kk++) {
            float w = wr[kk];
            a0+=w*sSh[0][kk]; a1+=w*sSh[1][kk]; a2+=w*sSh[2][kk]; a3+=w*sSh[3][kk];
            a4+=w*sSh[4][kk]; a5+=w*sSh[5][kk]; a6+=w*sSh[6][kk]; a7+=w*sSh[7][kk];
        }
        acc[gi][0]=a0; acc[gi][1]=a1; acc[gi][2]=a2; acc[gi][3]=a3;
        acc[gi][4]=a4; acc[gi][5]=a5; acc[gi][6]=a6; acc[gi][7]=a7;
    }
    #pragma unroll
    for (int r = 0; r < 8; r++) {
        int n = r0 + r;
        float ig = acc[0][r], fg = acc[1][r], gg = acc[2][r], og = acc[3][r];
        float c2 = sigm(fg)*g_c[n*HD+j] + sigm(ig)*tanhf(gg);
        g_c[n*HD+j] = c2;
        g_x[n*DP + j] = sigm(og)*tanhf(c2);
        if (j < 2) g_x[n*DP + HD + j] = sIn[r][j];
    }
}

// ---------------- Double-buffered GEMM: C = A(M=512 x K) @ B(N x K)^T ----------------
// TM=64, TN=32, 128 threads, 4x4/thread, K must be multiple of 16 (padded).
// flags: 1 = relu, 2 = add resid (stride ldc) after relu. splitK via gridDim.z.
#define TM 64
#define TN 32
__global__ __launch_bounds__(128) void k_gemm(
        const float* __restrict__ A, const float* __restrict__ B,
        const float* __restrict__ bias, const float* __restrict__ resid,
        float* __restrict__ C, int N, int lda, int ldb, int ldc,
        int kLen, int flags) {
    __shared__ float As[2][16][TM];
    __shared__ float Bs[2][16][TN];
    int tid = threadIdx.x;
    int tx = tid & 7, ty = tid >> 3;          // tx 0..7 (n), ty 0..15 (m)
    int bm = blockIdx.y * TM, bn = blockIdx.x * TN;
    int kStart = blockIdx.z * kLen;
    int nChunks = kLen >> 4;

    int lrow = tid >> 2;                      // 0..31
    int lk4  = tid & 3;                       // 0..3 (float4 slot in k-chunk)
    const float* Abase0 = A + (size_t)(bm + lrow)      * lda + kStart + lk4*4;
    const float* Abase1 = A + (size_t)(bm + lrow + 32) * lda + kStart + lk4*4;
    int gn = bn + lrow;
    const float* Bbase = B + (size_t)gn * ldb + kStart + lk4*4;
    bool bok = (gn < N);

    float4 pa0, pa1, pb0;
    // load chunk 0
    pa0 = *(const float4*)Abase0;
    pa1 = *(const float4*)Abase1;
    pb0 = bok ? *(const float4*)Bbase : make_float4(0.f,0.f,0.f,0.f);
    {
        As[0][lk4*4+0][lrow]=pa0.x; As[0][lk4*4+1][lrow]=pa0.y; As[0][lk4*4+2][lrow]=pa0.z; As[0][lk4*4+3][lrow]=pa0.w;
        As[0][lk4*4+0][lrow+32]=pa1.x; As[0][lk4*4+1][lrow+32]=pa1.y; As[0][lk4*4+2][lrow+32]=pa1.z; As[0][lk4*4+3][lrow+32]=pa1.w;
        Bs[0][lk4*4+0][lrow]=pb0.x; Bs[0][lk4*4+1][lrow]=pb0.y; Bs[0][lk4*4+2][lrow]=pb0.z; Bs[0][lk4*4+3][lrow]=pb0.w;
    }
    __syncthreads();

    float acc[4][4] = {};
    for (int c = 0; c < nChunks; c++) {
        int cur = c & 1;
        if (c + 1 < nChunks) {
            pa0 = *(const float4*)(Abase0 + (c+1)*16);
            pa1 = *(const float4*)(Abase1 + (c+1)*16);
            pb0 = bok ? *(const float4*)(Bbase + (c+1)*16) : make_float4(0.f,0.f,0.f,0.f);
        }
        #pragma unroll
        for (int kk = 0; kk < 16; kk++) {
            float4 av = *(const float4*)&As[cur][kk][ty*4];
            float4 bv = *(const float4*)&Bs[cur][kk][tx*4];
            acc[0][0]+=av.x*bv.x; acc[0][1]+=av.x*bv.y; acc[0][2]+=av.x*bv.z; acc[0][3]+=av.x*bv.w;
            acc[1][0]+=av.y*bv.x; acc[1][1]+=av.y*bv.y; acc[1][2]+=av.y*bv.z; acc[1][3]+=av.y*bv.w;
            acc[2][0]+=av.z*bv.x; acc[2][1]+=av.z*bv.y; acc[2][2]+=av.z*bv.z; acc[2][3]+=av.z*bv.w;
            acc[3][0]+=av.w*bv.x; acc[3][1]+=av.w*bv.y; acc[3][2]+=av.w*bv.z; acc[3][3]+=av.w*bv.w;
        }
        if (c + 1 < nChunks) {
            int nb = (c+1) & 1;
            As[nb][lk4*4+0][lrow]=pa0.x; As[nb][lk4*4+1][lrow]=pa0.y; As[nb][lk4*4+2][lrow]=pa0.z; As[nb][lk4*4+3][lrow]=pa0.w;
            As[nb][lk4*4+0][lrow+32]=pa1.x; As[nb][lk4*4+1][lrow+32]=pa1.y; As[nb][lk4*4+2][lrow+32]=pa1.z; As[nb][lk4*4+3][lrow+32]=pa1.w;
            Bs[nb][lk4*4+0][lrow]=pb0.x; Bs[nb][lk4*4+1][lrow]=pb0.y; Bs[nb][lk4*4+2][lrow]=pb0.z; Bs[nb][lk4*4+3][lrow]=pb0.w;
        }
        __syncthreads();
    }

    long zoff = (gridDim.z > 1) ? (long)blockIdx.z * NN * ldc : 0;
    #pragma unroll
    for (int i = 0; i < 4; i++) {
        int m = bm + ty*4 + i;                 // M = 512 always, exact
        #pragma unroll
        for (int jj = 0; jj < 4; jj++) {
            int n = bn + tx*4 + jj;
            if (n >= N) continue;
            float v = acc[i][jj];
            if (bias)      v += bias[n];
            if (flags & 1) v = fmaxf(v, 0.f);
            if (flags & 2) v += resid[(size_t)m*ldc + n];
            C[zoff + (size_t)m*ldc + n] = v;
        }
    }
}

// ---------------- Attention: 4 threads/token, KV resident in smem (per head) ----------------
// grid (NHEAD, NN/32), 128 threads. Skewed smem kills the 128-row bank aliasing.
#define ATT_SK (NN*DHD + 4)
__global__ __launch_bounds__(128) void k_attn(const float* __restrict__ qkv, float* __restrict__ att) {
    extern __shared__ float sm[];
    float* sK = sm;
    float* sV = sm + ATT_SK;
    int h = blockIdx.x;
    int bq = h*DHD, bk = DD + h*DHD, bv = 2*DD + h*DHD;
    int tid = threadIdx.x;
    for (int idx = tid; idx < NN*DHD; idx += 128) {
        int m = idx / DHD, c = idx - m*DHD;
        int sa = m*DHD + c + (m >> 7);
        sK[sa] = qkv[m*3*DD + bk + c];
        sV[sa] = qkv[m*3*DD + bv + c];
    }
    __syncthreads();

    int token = blockIdx.y*32 + (tid >> 2);
    int p = tid & 3;
    const float scale = rsqrtf((float)DHD);
    float q[DHD];
    #pragma unroll
    for (int c = 0; c < DHD; c++) q[c] = qkv[token*3*DD + bq + c] * scale;

    float mx = -1e30f, l = 0.f, acc[DHD];
    #pragma unroll
    for (int c = 0; c < DHD; c++) acc[c] = 0.f;
    int mbase = p * 128;
    for (int i = 0; i < 128; i++) {
        int m = mbase + i;
        const float* kr = &sK[m*DHD + p];
        const float* vr = &sV[m*DHD + p];
        float s = q[0]*kr[0];
        #pragma unroll
        for (int c = 1; c < DHD; c++) s += q[c]*kr[c];
        if (s <= mx) {
            float e = __expf(s - mx);
            l += e;
            #pragma unroll
            for (int c = 0; c < DHD; c++) acc[c] += e*vr[c];
        } else {
            float corr = __expf(mx - s);
            l = l*corr + 1.f;
            #pragma unroll
            for (int c = 0; c < DHD; c++) acc[c] = acc[c]*corr + vr[c];
            mx = s;
        }
    }
    // merge the 4 partials (lanes xor 1,2)
    #pragma unroll
    for (int off = 1; off < 4; off <<= 1) {
        float om = __shfl_xor_sync(0xffffffffu, mx, off);
        float ol = __shfl_xor_sync(0xffffffffu, l, off);
        float nm = fmaxf(mx, om);
        float c1 = __expf(mx - nm), c2 = __expf(om - nm);
        l = l*c1 + ol*c2;
        #pragma unroll
        for (int c = 0; c < DHD; c++) {
            float oa = __shfl_xor_sync(0xffffffffu, acc[c], off);
            acc[c] = acc[c]*c1 + oa*c2;
        }
        mx = nm;
    }
    if (p == 0) {
        float rl = 1.f / l;
        #pragma unroll
        for (int c = 0; c < DHD; c++) att[token*DP + bq + c] = acc[c]*rl;
    }
}

// ---------------- Add (+partials,+bias) then LayerNorm in place (stride DP) ----------------
__global__ void k_ln(float* __restrict__ x, const float* __restrict__ add, int P, int PS,
                     const float* __restrict__ bias,
                     const float* __restrict__ s, const float* __restrict__ b) {
    __shared__ float red1[8], red2[8];
    int row = blockIdx.x, tid = threadIdx.x;
    bool valid = tid < DD;
    float v = 0.f;
    if (valid) {
        v = x[row*DP + tid];
        if (bias) v += bias[tid];
        for (int p = 0; p < P; p++) v += add[(long)p*PS + row*DP + tid];
    }
    float s1 = v, s2 = v*v;
    #pragma unroll
    for (int o = 16; o; o >>= 1) {
        s1 += __shfl_down_sync(0xffffffffu, s1, o);
        s2 += __shfl_down_sync(0xffffffffu, s2, o);
    }
    if ((tid & 31) == 0) { red1[tid>>5] = s1; red2[tid>>5] = s2; }
    __syncthreads();
    if (tid < 8) {
        s1 = red1[tid]; s2 = red2[tid];
        #pragma unroll
        for (int o = 4; o; o >>= 1) {
            s1 += __shfl_down_sync(0xffu, s1, o);
            s2 += __shfl_down_sync(0xffu, s2, o);
        }
        if (tid == 0) { red1[0] = s1; red2[0] = s2; }
    }
    __syncthreads();
    float mean = red1[0] * (1.f/DD);
    float var  = red2[0] * (1.f/DD) - mean*mean;
    float rstd = rsqrtf(var + 1e-5f);
    if (valid) x[row*DP + tid] = (v - mean)*rstd*s[tid] + b[tid];
}

// ---------------- Rollout head ----------------
__global__ void k_head(const float* __restrict__ mlp2, const float* __restrict__ W_pl,
                       const float* __restrict__ b_pl,
                       const float* __restrict__ cf, int cfStride,
                       float* __restrict__ outp) {
    int n = blockIdx.x*blockDim.x + threadIdx.x;
    if (n >= NN) return;
    const float* xr = mlp2 + n*HD;
    float a0 = b_pl[0], a1 = b_pl[1];
    #pragma unroll 4
    for (int k = 0; k < HD; k++) {
        a0 += xr[k]*W_pl[k];
        a1 += xr[k]*W_pl[HD+k];
    }
    const float* c = cf + n*cfStride;
    const float DT = 0.1f;
    float v0 = a0*DT + c[2], v1 = a1*DT + c[3];
    float p0 = a0*(DT*DT*0.5f) + v0*DT + c[0];
    float p1 = a1*(DT*DT*0.5f) + v1*DT + c[1];
    outp[n*(PLEN*4)+0] = p0; outp[n*(PLEN*4)+1] = p1;
    outp[n*(PLEN*4)+2] = v0; outp[n*(PLEN*4)+3] = v1;
    g_inp[n*4+0] = p0; g_inp[n*4+1] = p1; g_inp[n*4+2] = v0; g_inp[n*4+3] = v1;
}

// ---------------- Host orchestration ----------------
extern "C" void kernel_launch(void* const* d_in, const int* in_sizes, int n_in,
                              void* d_out, int out_size) {
    const float* Tracks = (const float*)d_in[0];
    const float* W_emb  = (const float*)d_in[1];
    const float* b_emb  = (const float*)d_in[2];
    const float* W_ih   = (const float*)d_in[3];
    const float* W_hh   = (const float*)d_in[4];
    const float* b_ih   = (const float*)d_in[5];
    const float* b_hh   = (const float*)d_in[6];
    const float* qkv_w  = (const float*)d_in[7];
    const float* qkv_b  = (const float*)d_in[8];
    const float* out_w  = (const float*)d_in[9];
    const float* out_b  = (const float*)d_in[10];
    const float* ff1_w  = (const float*)d_in[11];
    const float* ff1_b  = (const float*)d_in[12];
    const float* ff2_w  = (const float*)d_in[13];
    const float* ff2_b  = (const float*)d_in[14];
    const float* ln1_s  = (const float*)d_in[15];
    const float* ln1_b  = (const float*)d_in[16];
    const float* ln2_s  = (const float*)d_in[17];
    const float* ln2_b  = (const float*)d_in[18];
    const float* W_sp   = (const float*)d_in[19];
    const float* b_sp   = (const float*)d_in[20];
    const float* W_p1   = (const float*)d_in[21];
    const float* b_p1   = (const float*)d_in[22];
    const float* W_p2   = (const float*)d_in[23];
    const float* b_p2   = (const float*)d_in[24];
    const float* W_pl   = (const float*)d_in[25];
    const float* b_pl   = (const float*)d_in[26];
    float* out = (float*)d_out;

    const int ATTN_SMEM = 2*ATT_SK*(int)sizeof(float);
    cudaFuncSetAttribute(k_attn, cudaFuncAttributeMaxDynamicSharedMemorySize, 56*1024);

    float *xp, *qkvp, *attp, *tmpp, *ff1p, *partp, *Shp, *m1p, *m2p, *inpp;
    float *qkvP, *outP, *ff1P, *spP;
    cudaGetSymbolAddress((void**)&xp,    g_x);
    cudaGetSymbolAddress((void**)&qkvp,  g_qkv);
    cudaGetSymbolAddress((void**)&attp,  g_att);
    cudaGetSymbolAddress((void**)&tmpp,  g_tmp);
    cudaGetSymbolAddress((void**)&ff1p,  g_ff1);
    cudaGetSymbolAddress((void**)&partp, g_part);
    cudaGetSymbolAddress((void**)&Shp,   g_Sh);
    cudaGetSymbolAddress((void**)&m1p,   g_mlp1);
    cudaGetSymbolAddress((void**)&m2p,   g_mlp2);
    cudaGetSymbolAddress((void**)&inpp,  g_inp);
    cudaGetSymbolAddress((void**)&qkvP,  g_qkvP);
    cudaGetSymbolAddress((void**)&outP,  g_outP);
    cudaGetSymbolAddress((void**)&ff1P,  g_ff1P);
    cudaGetSymbolAddress((void**)&spP,   g_spP);

    // gemm launcher: M fixed at 512, K multiple of 16
    auto gemm = [&](const float* A, const float* B, const float* bias, const float* resid,
                    float* C, int Nn, int lda, int ldb, int ldc,
                    int K, int splitK, int flags) {
        dim3 grid((Nn + TN - 1)/TN, NN/TM, splitK);
        k_gemm<<<grid, 128>>>(A, B, bias, resid, C, Nn, lda, ldb, ldc, K/splitK, flags);
    };

    auto sp = [&]() {
        for (int j = 0; j < NLAY; j++) {
            gemm(xp, qkvP + (size_t)j*3*DD*DP, qkv_b + j*3*DD, nullptr, qkvp,
                 3*DD, DP, DP, 3*DD, DP, 1, 0);
            k_attn<<<dim3(NHEAD, NN/32), 128, ATTN_SMEM>>>(qkvp, attp);
            gemm(attp, outP + (size_t)j*DD*DP, out_b + j*DD, nullptr, tmpp,
                 DD, DP, DP, DP, DP, 1, 0);
            k_ln<<<NN, 256>>>(xp, tmpp, 1, 0, nullptr, ln1_s + j*DD, ln1_b + j*DD);
            gemm(xp, ff1P + (size_t)j*FFD*DP, ff1_b + j*FFD, nullptr, ff1p,
                 FFD, DP, DP, FFD, DP, 1, 1);
            gemm(ff1p, ff2_w + (size_t)j*DD*FFD, nullptr, nullptr, partp,
                 DD, FFD, FFD, DP, FFD, 8, 0);
            k_ln<<<NN, 256>>>(xp, partp, 8, NN*DP, ff2_b + j*DD, ln2_s + j*DD, ln2_b + j*DD);
        }
        gemm(xp, spP, b_sp, nullptr, Shp, HD, DP, DP, HD, DP, 1, 0);
    };

    k_setup<<<1, 4*HD>>>(W_ih, W_emb, b_emb, b_ih, b_hh);
    k_init<<<(NN*DP + 255)/256, 256>>>();
    k_repack<<<(RP_ROWS*DP + 255)/256, 256>>>(qkv_w, out_w, ff1_w, W_sp);

    // initial step (Sh=c=0), input Tracks[:,0,1:]
    k_lstm<<<NN/8, HD>>>(W_hh, Tracks + 1, LHIST*5);
    sp();
    // history scan
    for (int t = 0; t < LHIST; t++) {
        k_lstm<<<NN/8, HD>>>(W_hh, Tracks + t*5 + 1, LHIST*5);
        sp();
    }
    // rollout
    for (int t = 0; t < PLEN; t++) {
        gemm(Shp, W_p1, b_p1, Shp, m1p, HD, HD, HD, HD, HD, 1, 3);
        gemm(m1p, W_p2, b_p2, m1p, m2p, HD, HD, HD, HD, HD, 1, 3);
        const float* cf = (t == 0) ? (Tracks + (LHIST-1)*5 + 1) : inpp;
        int cfs = (t == 0) ? LHIST*5 : 4;
        k_head<<<2, 256>>>(m2p, W_pl, b_pl, cf, cfs, out + t*4);
        if (t < PLEN - 1) {          // last rm_sp's carry is discarded by the scan
            k_lstm<<<NN/8, HD>>>(W_hh, inpp, 4);
            sp();
        }
    }
}

// round 5
// speedup vs baseline: 1.7737x; 1.7223x over previous
#include <cuda_runtime.h>
#include <cuda_bf16.h>
#include <math.h>

// ---------------- Problem constants ----------------
#define NN    512
#define LHIST 20
#define PLEN  10
#define HD    128      // H
#define ED    64       // E
#define NHEAD 10
#define FFD   2048
#define DD    130      // D = H+2
#define DP    144      // padded D (multiple of 16)
#define DHD   13       // D / NH
#define NLAY  3
#define GRID  132      // persistent blocks (< 148 SMs, all resident)
#define NT    256      // threads per block

// ---------------- Device state ----------------
__device__ float g_Wcomb[4*HD*4];
__device__ float g_bcomb[4*HD];
__device__ float g_x[NN*DP];
__device__ float g_Sh[NN*HD];
__device__ float g_c[NN*HD];
__device__ float g_gates[NN*4*HD];
__device__ float g_qkv[NN*3*DD];
__device__ float g_att[NN*DP];
__device__ float g_tmp[NN*DP];
__device__ float g_ff1[NN*FFD];
__device__ float g_part[4*NN*DP];
__device__ float g_mlp1[NN*HD];
__device__ float g_mlp2[NN*HD];
__device__ float g_inp[NN*4];
// Repacked weights (K 130 -> 144)
__device__ float g_qkvP[NLAY*3*DD*DP];
__device__ float g_outP[NLAY*DD*DP];
__device__ float g_ff1P[NLAY*FFD*DP];
__device__ float g_spP[HD*DP];
// Grid barrier
__device__ volatile unsigned g_gen;
__device__ unsigned g_cnt;

__device__ __forceinline__ float sigm(float x){ return 1.f/(1.f+expf(-x)); }

// ---------------- Grid-wide barrier (all GRID blocks resident) ----------------
__device__ __forceinline__ void gridbar() {
    __syncthreads();
    if (threadIdx.x == 0) {
        unsigned old = g_gen;
        __threadfence();
        if (atomicAdd(&g_cnt, 1u) == GRID - 1) {
            g_cnt = 0;
            __threadfence();
            g_gen = old + 1;
        } else {
            while (g_gen == old) { __nanosleep(32); }
        }
        __threadfence();
    }
    __syncthreads();
}

// ---------------- Tiled GEMM phase: C = A(512 x K) @ B(N x K)^T ----------------
// 64x64 tile, 256 threads, 4x4/thread, double-buffered, K multiple of 16.
// flags: 1 = relu, 2 = add resid. splitK>1: write partials (no bias) at z*NN*ldc.
#define SST 68              // smem row stride (floats), 16B-aligned, low conflict
#define SBUF (16*SST)       // one k-chunk buffer
__device__ void dgemm(const float* __restrict__ A, const float* __restrict__ B,
                      const float* __restrict__ bias, const float* __restrict__ resid,
                      float* __restrict__ C, int N, int lda, int ldb, int ldc,
                      int K, int splitK, int flags, float* sm)
{
    const int tilesM = NN/64;                 // M is always 512
    int tilesN = (N + 63) >> 6;
    int total = tilesM * tilesN * splitK;
    int kLen = K / splitK;
    int nCh = kLen >> 4;
    float* As = sm;
    float* Bs = sm + 2*SBUF;
    int tid = threadIdx.x;
    int lrow = tid >> 2, lk4 = (tid & 3) * 4;
    int tx = (tid & 15) * 4, ty = (tid >> 4) * 4;

    for (int u = blockIdx.x; u < total; u += GRID) {
        int z  = u / (tilesM * tilesN);
        int r  = u - z * (tilesM * tilesN);
        int bm = (r / tilesN) * 64, bn = (r % tilesN) * 64;
        int kS = z * kLen;
        const float* Ab = A + (size_t)(bm + lrow) * lda + kS + lk4;
        int gn = bn + lrow;
        const float* Bb = B + (size_t)gn * ldb + kS + lk4;
        bool bok = gn < N;

        float4 pa = *(const float4*)Ab;
        float4 pb = bok ? *(const float4*)Bb : make_float4(0.f,0.f,0.f,0.f);
        As[(lk4+0)*SST+lrow]=pa.x; As[(lk4+1)*SST+lrow]=pa.y;
        As[(lk4+2)*SST+lrow]=pa.z; As[(lk4+3)*SST+lrow]=pa.w;
        Bs[(lk4+0)*SST+lrow]=pb.x; Bs[(lk4+1)*SST+lrow]=pb.y;
        Bs[(lk4+2)*SST+lrow]=pb.z; Bs[(lk4+3)*SST+lrow]=pb.w;
        __syncthreads();

        float acc[4][4] = {};
        for (int c = 0; c < nCh; c++) {
            int cur = (c & 1) * SBUF;
            if (c + 1 < nCh) {
                pa = *(const float4*)(Ab + (c+1)*16);
                pb = bok ? *(const float4*)(Bb + (c+1)*16) : make_float4(0.f,0.f,0.f,0.f);
            }
            #pragma unroll
            for (int kk = 0; kk < 16; kk++) {
                float4 av = *(const float4*)&As[cur + kk*SST + ty];
                float4 bv = *(const float4*)&Bs[cur + kk*SST + tx];
                acc[0][0]+=av.x*bv.x; acc[0][1]+=av.x*bv.y; acc[0][2]+=av.x*bv.z; acc[0][3]+=av.x*bv.w;
                acc[1][0]+=av.y*bv.x; acc[1][1]+=av.y*bv.y; acc[1][2]+=av.y*bv.z; acc[1][3]+=av.y*bv.w;
                acc[2][0]+=av.z*bv.x; acc[2][1]+=av.z*bv.y; acc[2][2]+=av.z*bv.z; acc[2][3]+=av.z*bv.w;
                acc[3][0]+=av.w*bv.x; acc[3][1]+=av.w*bv.y; acc[3][2]+=av.w*bv.z; acc[3][3]+=av.w*bv.w;
            }
            if (c + 1 < nCh) {
                int nb = ((c+1) & 1) * SBUF;
                As[nb+(lk4+0)*SST+lrow]=pa.x; As[nb+(lk4+1)*SST+lrow]=pa.y;
                As[nb+(lk4+2)*SST+lrow]=pa.z; As[nb+(lk4+3)*SST+lrow]=pa.w;
                Bs[nb+(lk4+0)*SST+lrow]=pb.x; Bs[nb+(lk4+1)*SST+lrow]=pb.y;
                Bs[nb+(lk4+2)*SST+lrow]=pb.z; Bs[nb+(lk4+3)*SST+lrow]=pb.w;
            }
            __syncthreads();
        }

        size_t zoff = (splitK > 1) ? (size_t)z * NN * ldc : 0;
        #pragma unroll
        for (int i = 0; i < 4; i++) {
            int m = bm + ty + i;
            #pragma unroll
            for (int jj = 0; jj < 4; jj++) {
                int n = bn + tx + jj;
                if (n >= N) continue;
                float v = acc[i][jj];
                if (bias)      v += bias[n];
                if (flags & 1) v = fmaxf(v, 0.f);
                if (flags & 2) v += resid[(size_t)m*ldc + n];
                C[zoff + (size_t)m*ldc + n] = v;
            }
        }
        __syncthreads();
    }
}

// ---------------- Attention phase: KV in smem, 4 partials/token ----------------
#define ATT_SK (NN*DHD + 4)
__device__ void dattn(float* sm) {
    float* sK = sm;
    float* sV = sm + ATT_SK;
    int tid = threadIdx.x;
    for (int u = blockIdx.x; u < NHEAD*8; u += GRID) {
        int h = u >> 3, chunk = u & 7;
        int bq = h*DHD, bk = DD + h*DHD, bv = 2*DD + h*DHD;
        for (int idx = tid; idx < NN*DHD; idx += NT) {
            int m = idx / DHD, c = idx - m*DHD;
            int sa = idx + (m >> 7);
            sK[sa] = g_qkv[m*3*DD + bk + c];
            sV[sa] = g_qkv[m*3*DD + bv + c];
        }
        __syncthreads();

        int token = chunk*64 + (tid >> 2);
        int p = tid & 3;
        const float scale = rsqrtf((float)DHD);
        float q[DHD];
        #pragma unroll
        for (int c = 0; c < DHD; c++) q[c] = g_qkv[token*3*DD + bq + c] * scale;

        float mx = -1e30f, l = 0.f, acc[DHD];
        #pragma unroll
        for (int c = 0; c < DHD; c++) acc[c] = 0.f;
        int mbase = p * 128;
        for (int i = 0; i < 128; i++) {
            int m = mbase + i;
            const float* kr = &sK[m*DHD + p];
            const float* vr = &sV[m*DHD + p];
            float s = q[0]*kr[0];
            #pragma unroll
            for (int c = 1; c < DHD; c++) s += q[c]*kr[c];
            if (s <= mx) {
                float e = __expf(s - mx);
                l += e;
                #pragma unroll
                for (int c = 0; c < DHD; c++) acc[c] += e*vr[c];
            } else {
                float corr = __expf(mx - s);
                l = l*corr + 1.f;
                #pragma unroll
                for (int c = 0; c < DHD; c++) acc[c] = acc[c]*corr + vr[c];
                mx = s;
            }
        }
        #pragma unroll
        for (int off = 1; off < 4; off <<= 1) {
            float om = __shfl_xor_sync(0xffffffffu, mx, off);
            float ol = __shfl_xor_sync(0xffffffffu, l, off);
            float nm = fmaxf(mx, om);
            float c1 = __expf(mx - nm), c2 = __expf(om - nm);
            l = l*c1 + ol*c2;
            #pragma unroll
            for (int c = 0; c < DHD; c++) {
                float oa = __shfl_xor_sync(0xffffffffu, acc[c], off);
                acc[c] = acc[c]*c1 + oa*c2;
            }
            mx = nm;
        }
        if (p == 0) {
            float rl = 1.f / l;
            #pragma unroll
            for (int c = 0; c < DHD; c++) g_att[token*DP + bq + c] = acc[c]*rl;
        }
        __syncthreads();
    }
}

// ---------------- LayerNorm phase: warp per row, x = LN(x + add(+bias)) ----------------
__device__ void dln(const float* __restrict__ add, int P, const float* __restrict__ bias,
                    const float* __restrict__ s, const float* __restrict__ b)
{
    int w = blockIdx.x * (NT/32) + (threadIdx.x >> 5);
    int lane = threadIdx.x & 31;
    if (w >= NN) return;
    float v[5];
    float s1 = 0.f, s2 = 0.f;
    #pragma unroll
    for (int i = 0; i < 5; i++) {
        int idx = lane + i*32;
        float xv = 0.f;
        if (idx < DD) {
            xv = g_x[w*DP + idx];
            if (bias) xv += bias[idx];
            for (int p = 0; p < P; p++) xv += add[(size_t)p*NN*DP + w*DP + idx];
        }
        v[i] = xv; s1 += xv; s2 += xv*xv;
    }
    #pragma unroll
    for (int o = 16; o; o >>= 1) {
        s1 += __shfl_xor_sync(0xffffffffu, s1, o);
        s2 += __shfl_xor_sync(0xffffffffu, s2, o);
    }
    float mean = s1 * (1.f/DD);
    float var  = s2 * (1.f/DD) - mean*mean;
    float rstd = rsqrtf(var + 1e-5f);
    #pragma unroll
    for (int i = 0; i < 5; i++) {
        int idx = lane + i*32;
        if (idx < DD) g_x[w*DP + idx] = (v[i] - mean)*rstd*s[idx] + b[idx];
    }
}

// ---------------- LSTM pointwise (after gates GEMM) ----------------
__device__ void dlstm_pt(const float* __restrict__ inp, int istride) {
    for (int e = blockIdx.x*NT + threadIdx.x; e < NN*HD; e += GRID*NT) {
        int n = e >> 7, j = e & 127;
        float in0 = inp[n*istride+0], in1 = inp[n*istride+1];
        float in2 = inp[n*istride+2], in3 = inp[n*istride+3];
        float g[4];
        #pragma unroll
        for (int gi = 0; gi < 4; gi++) {
            int row = gi*HD + j;
            g[gi] = g_gates[n*(4*HD) + row] + g_bcomb[row]
                  + g_Wcomb[row*4+0]*in0 + g_Wcomb[row*4+1]*in1
                  + g_Wcomb[row*4+2]*in2 + g_Wcomb[row*4+3]*in3;
        }
        float c2 = sigm(g[1])*g_c[e] + sigm(g[0])*tanhf(g[2]);
        g_c[e] = c2;
        g_x[n*DP + j] = sigm(g[3])*tanhf(c2);
        if (j < 2) g_x[n*DP + HD + j] = (j == 0) ? in0 : in1;
    }
}

// ---------------- Rollout head ----------------
__device__ void dhead(const float* __restrict__ W_pl, const float* __restrict__ b_pl,
                      const float* __restrict__ cf, int cfs, float* __restrict__ outp)
{
    int n = blockIdx.x*NT + threadIdx.x;
    if (n >= NN) return;
    const float* xr = g_mlp2 + n*HD;
    float a0 = b_pl[0], a1 = b_pl[1];
    #pragma unroll 4
    for (int k = 0; k < HD; k++) {
        a0 += xr[k]*W_pl[k];
        a1 += xr[k]*W_pl[HD+k];
    }
    const float* c = cf + n*cfs;
    const float DT = 0.1f;
    float v0 = a0*DT + c[2], v1 = a1*DT + c[3];
    float p0 = a0*(DT*DT*0.5f) + v0*DT + c[0];
    float p1 = a1*(DT*DT*0.5f) + v1*DT + c[1];
    outp[n*(PLEN*4)+0] = p0; outp[n*(PLEN*4)+1] = p1;
    outp[n*(PLEN*4)+2] = v0; outp[n*(PLEN*4)+3] = v1;
    g_inp[n*4+0] = p0; g_inp[n*4+1] = p1; g_inp[n*4+2] = v0; g_inp[n*4+3] = v1;
}

// ---------------- Setup: fold emb, zero state, repack weights ----------------
#define RP_ROWS (NLAY*3*DD + NLAY*DD + NLAY*FFD + HD)
__device__ void dsetup(const float* W_ih, const float* W_emb, const float* b_emb,
                       const float* b_ih, const float* b_hh,
                       const float* qkv_w, const float* out_w,
                       const float* ff1_w, const float* W_sp)
{
    int gtid = blockIdx.x*NT + threadIdx.x;
    const int nthr = GRID*NT;
    for (int j = gtid; j < 4*HD; j += nthr) {
        float wc0=0.f, wc1=0.f, wc2=0.f, wc3=0.f;
        float bb = b_ih[j] + b_hh[j];
        #pragma unroll 8
        for (int e = 0; e < ED; e++) {
            float w = W_ih[j*ED + e];
            bb  += w * b_emb[e];
            wc0 += w * W_emb[e*4 + 0];
            wc1 += w * W_emb[e*4 + 1];
            wc2 += w * W_emb[e*4 + 2];
            wc3 += w * W_emb[e*4 + 3];
        }
        g_Wcomb[j*4+0]=wc0; g_Wcomb[j*4+1]=wc1; g_Wcomb[j*4+2]=wc2; g_Wcomb[j*4+3]=wc3;
        g_bcomb[j]=bb;
    }
    for (int i = gtid; i < NN*HD; i += nthr) { g_Sh[i] = 0.f; g_c[i] = 0.f; }
    for (int i = gtid; i < NN*DP; i += nthr) { g_x[i] = 0.f; g_att[i] = 0.f; }
    for (int idx = gtid; idx < RP_ROWS*DP; idx += nthr) {
        int row = idx / DP, k = idx - row*DP;
        const float* src; float* dst; int r;
        if (row < NLAY*3*DD)                         { src = qkv_w; dst = g_qkvP; r = row; }
        else if (row < NLAY*3*DD+NLAY*DD)            { src = out_w; dst = g_outP; r = row - NLAY*3*DD; }
        else if (row < NLAY*3*DD+NLAY*DD+NLAY*FFD)   { src = ff1_w; dst = g_ff1P; r = row - NLAY*3*DD - NLAY*DD; }
        else                                         { src = W_sp;  dst = g_spP;  r = row - NLAY*3*DD - NLAY*DD - NLAY*FFD; }
        dst[r*DP + k] = (k < DD) ? src[r*DD + k] : 0.f;
    }
}

// ---------------- Encoder stack (sp) ----------------
__device__ void dsp(const float* qkv_b, const float* out_b, const float* ff1_b,
                    const float* ff2_w, const float* ff2_b,
                    const float* ln1_s, const float* ln1_b,
                    const float* ln2_s, const float* ln2_b,
                    const float* b_sp, float* sm)
{
    for (int j = 0; j < NLAY; j++) {
        dgemm(g_x, g_qkvP + (size_t)j*3*DD*DP, qkv_b + j*3*DD, nullptr, g_qkv,
              3*DD, DP, DP, 3*DD, DP, 1, 0, sm);
        gridbar();
        dattn(sm);
        gridbar();
        dgemm(g_att, g_outP + (size_t)j*DD*DP, out_b + j*DD, nullptr, g_tmp,
              DD, DP, DP, DP, DP, 1, 0, sm);
        gridbar();
        dln(g_tmp, 1, nullptr, ln1_s + j*DD, ln1_b + j*DD);
        gridbar();
        dgemm(g_x, g_ff1P + (size_t)j*FFD*DP, ff1_b + j*FFD, nullptr, g_ff1,
              FFD, DP, DP, FFD, DP, 1, 1, sm);
        gridbar();
        dgemm(g_ff1, ff2_w + (size_t)j*DD*FFD, nullptr, nullptr, g_part,
              DD, FFD, FFD, DP, FFD, 4, 0, sm);
        gridbar();
        dln(g_part, 4, ff2_b + j*DD, ln2_s + j*DD, ln2_b + j*DD);
        gridbar();
    }
    dgemm(g_x, g_spP, b_sp, nullptr, g_Sh, HD, DP, DP, HD, DP, 1, 0, sm);
    gridbar();
}

// ---------------- Megakernel ----------------
__global__ void __launch_bounds__(NT) mega(
    const float* Tracks, const float* W_emb, const float* b_emb,
    const float* W_ih, const float* W_hh, const float* b_ih, const float* b_hh,
    const float* qkv_w, const float* qkv_b, const float* out_w, const float* out_b,
    const float* ff1_w, const float* ff1_b, const float* ff2_w, const float* ff2_b,
    const float* ln1_s, const float* ln1_b, const float* ln2_s, const float* ln2_b,
    const float* W_sp, const float* b_sp, const float* W_p1, const float* b_p1,
    const float* W_p2, const float* b_p2, const float* W_pl, const float* b_pl,
    float* out)
{
    extern __shared__ float sm[];
    dsetup(W_ih, W_emb, b_emb, b_ih, b_hh, qkv_w, out_w, ff1_w, W_sp);
    gridbar();

    // initial step (t = -1 uses Tracks[:,0,1:], same column as t=0)
    for (int t = -1; t < LHIST; t++) {
        const float* ib = (t < 0) ? (Tracks + 1) : (Tracks + t*5 + 1);
        dgemm(g_Sh, W_hh, nullptr, nullptr, g_gates, 4*HD, HD, HD, 4*HD, HD, 1, 0, sm);
        gridbar();
        dlstm_pt(ib, LHIST*5);
        gridbar();
        dsp(qkv_b, out_b, ff1_b, ff2_w, ff2_b, ln1_s, ln1_b, ln2_s, ln2_b, b_sp, sm);
    }
    // rollout
    for (int t = 0; t < PLEN; t++) {
        dgemm(g_Sh, W_p1, b_p1, g_Sh, g_mlp1, HD, HD, HD, HD, HD, 1, 3, sm);
        gridbar();
        dgemm(g_mlp1, W_p2, b_p2, g_mlp1, g_mlp2, HD, HD, HD, HD, HD, 1, 3, sm);
        gridbar();
        dhead(W_pl, b_pl, (t == 0) ? (Tracks + (LHIST-1)*5 + 1) : g_inp,
              (t == 0) ? LHIST*5 : 4, out + t*4);
        gridbar();
        if (t < PLEN - 1) {     // last rm_sp's carry is discarded by the scan
            dgemm(g_Sh, W_hh, nullptr, nullptr, g_gates, 4*HD, HD, HD, 4*HD, HD, 1, 0, sm);
            gridbar();
            dlstm_pt(g_inp, 4);
            gridbar();
            dsp(qkv_b, out_b, ff1_b, ff2_w, ff2_b, ln1_s, ln1_b, ln2_s, ln2_b, b_sp, sm);
        }
    }
}

// ---------------- Host ----------------
extern "C" void kernel_launch(void* const* d_in, const int* in_sizes, int n_in,
                              void* d_out, int out_size) {
    const float* Tracks = (const float*)d_in[0];
    const float* W_emb  = (const float*)d_in[1];
    const float* b_emb  = (const float*)d_in[2];
    const float* W_ih   = (const float*)d_in[3];
    const float* W_hh   = (const float*)d_in[4];
    const float* b_ih   = (const float*)d_in[5];
    const float* b_hh   = (const float*)d_in[6];
    const float* qkv_w  = (const float*)d_in[7];
    const float* qkv_b  = (const float*)d_in[8];
    const float* out_w  = (const float*)d_in[9];
    const float* out_b  = (const float*)d_in[10];
    const float* ff1_w  = (const float*)d_in[11];
    const float* ff1_b  = (const float*)d_in[12];
    const float* ff2_w  = (const float*)d_in[13];
    const float* ff2_b  = (const float*)d_in[14];
    const float* ln1_s  = (const float*)d_in[15];
    const float* ln1_b  = (const float*)d_in[16];
    const float* ln2_s  = (const float*)d_in[17];
    const float* ln2_b  = (const float*)d_in[18];
    const float* W_sp   = (const float*)d_in[19];
    const float* b_sp   = (const float*)d_in[20];
    const float* W_p1   = (const float*)d_in[21];
    const float* b_p1   = (const float*)d_in[22];
    const float* W_p2   = (const float*)d_in[23];
    const float* b_p2   = (const float*)d_in[24];
    const float* W_pl   = (const float*)d_in[25];
    const float* b_pl   = (const float*)d_in[26];
    float* out = (float*)d_out;

    // smem = max(attention KV: 2*(512*13+4)*4 = 53280B, gemm: 4*16*68*4 = 17408B)
    const int SMEM = 2*ATT_SK*(int)sizeof(float);
    static int configured = 0;
    if (!configured) {
        cudaFuncSetAttribute(mega, cudaFuncAttributeMaxDynamicSharedMemorySize, SMEM);
        configured = 1;
    }

    mega<<<GRID, NT, SMEM>>>(Tracks, W_emb, b_emb, W_ih, W_hh, b_ih, b_hh,
                             qkv_w, qkv_b, out_w, out_b, ff1_w, ff1_b, ff2_w, ff2_b,
                             ln1_s, ln1_b, ln2_s, ln2_b, W_sp, b_sp,
                             W_p1, b_p1, W_p2, b_p2, W_pl, b_pl, out);
}

// round 6
// speedup vs baseline: 1.8575x; 1.0473x over previous
#include <cuda_runtime.h>
#include <cuda_bf16.h>
#include <math.h>

// ---------------- Problem constants ----------------
#define NN    512
#define LHIST 20
#define PLEN  10
#define HD    128      // H
#define ED    64       // E
#define NHEAD 10
#define FFD   2048
#define DD    130      // D = H+2
#define DP    144      // padded D (multiple of 16)
#define DHD   13       // D / NH
#define NLAY  3
#define GRID  264      // persistent blocks: 2 per SM on 132 SMs (<=148)
#define NT    256      // threads per block

// ---------------- Device state ----------------
__device__ float g_Wcomb[4*HD*4];
__device__ float g_bcomb[4*HD];
__device__ float g_x[NN*DP];
__device__ float g_Sh[NN*HD];
__device__ float g_c[NN*HD];
__device__ float g_gates[NN*4*HD];
__device__ float g_qkv[NN*3*DD];
__device__ float g_att[NN*DP];
__device__ float g_tmp[NN*DP];
__device__ float g_ff1[NN*FFD];
__device__ float g_part[8*NN*DP];
__device__ float g_mlp1[NN*HD];
__device__ float g_mlp2[NN*HD];
__device__ float g_inp[NN*4];
// Repacked weights (K 130 -> 144)
__device__ float g_qkvP[NLAY*3*DD*DP];
__device__ float g_outP[NLAY*DD*DP];
__device__ float g_ff1P[NLAY*FFD*DP];
__device__ float g_spP[HD*DP];
// Fused gate weights: Wf = W_hh @ W_sp (512 x 144), bspW = W_hh @ b_sp
__device__ float g_Wf[4*HD*DP];
__device__ float g_bspW[4*HD];
// Grid barrier
__device__ volatile unsigned g_gen;
__device__ unsigned g_cnt;

__device__ __forceinline__ float sigm(float x){ return 1.f/(1.f+expf(-x)); }

// ---------------- Grid-wide barrier (all GRID blocks resident) ----------------
__device__ __forceinline__ void gridbar() {
    __syncthreads();
    if (threadIdx.x == 0) {
        unsigned old = g_gen;
        __threadfence();
        if (atomicAdd(&g_cnt, 1u) == GRID - 1) {
            g_cnt = 0;
            __threadfence();
            g_gen = old + 1;
        } else {
            while (g_gen == old) { __nanosleep(32); }
        }
        __threadfence();
    }
    __syncthreads();
}

// ---------------- Tiled GEMM phase: C = A(512 x K) @ B(N x K)^T ----------------
// TMv in {32,64} x TN=64 tile, 256 threads, double-buffered, K multiple of 16.
// flags: 1 = relu, 2 = add resid. splitK>1: write partials (no bias) at z*NN*ldc.
#define SST 68              // smem row stride (floats)
#define SBUF (16*SST)       // one k-chunk buffer
template<int TMv>
__device__ void dgemm_t(const float* __restrict__ A, const float* __restrict__ B,
                        const float* __restrict__ bias, const float* __restrict__ resid,
                        float* __restrict__ C, int N, int lda, int ldb, int ldc,
                        int K, int splitK, int flags, float* sm)
{
    const int MR = TMv/16;                    // rows per thread (4 or 2)
    const int tilesM = NN/TMv;
    int tilesN = (N + 63) >> 6;
    int total = tilesM * tilesN * splitK;
    int kLen = K / splitK;
    int nCh = kLen >> 4;
    float* As = sm;
    float* Bs = sm + 2*SBUF;
    int tid = threadIdx.x;
    int lrow = tid >> 2, lk4 = (tid & 3) * 4;
    int tx = (tid & 15) * 4, ty = (tid >> 4) * MR;
    bool aload = (TMv == 64) || (tid < 128);

    for (int u = blockIdx.x; u < total; u += GRID) {
        int z  = u / (tilesM * tilesN);
        int r  = u - z * (tilesM * tilesN);
        int bm = (r / tilesN) * TMv, bn = (r % tilesN) * 64;
        int kS = z * kLen;
        const float* Ab = A + (size_t)(bm + lrow) * lda + kS + lk4;
        int gn = bn + lrow;
        const float* Bb = B + (size_t)gn * ldb + kS + lk4;
        bool bok = gn < N;

        float4 pa = make_float4(0.f,0.f,0.f,0.f), pb;
        if (aload) pa = *(const float4*)Ab;
        pb = bok ? *(const float4*)Bb : make_float4(0.f,0.f,0.f,0.f);
        if (aload) {
            As[(lk4+0)*SST+lrow]=pa.x; As[(lk4+1)*SST+lrow]=pa.y;
            As[(lk4+2)*SST+lrow]=pa.z; As[(lk4+3)*SST+lrow]=pa.w;
        }
        Bs[(lk4+0)*SST+lrow]=pb.x; Bs[(lk4+1)*SST+lrow]=pb.y;
        Bs[(lk4+2)*SST+lrow]=pb.z; Bs[(lk4+3)*SST+lrow]=pb.w;
        __syncthreads();

        float acc[MR][4];
        #pragma unroll
        for (int i = 0; i < MR; i++)
            #pragma unroll
            for (int jj = 0; jj < 4; jj++) acc[i][jj] = 0.f;

        for (int c = 0; c < nCh; c++) {
            int cur = (c & 1) * SBUF;
            if (c + 1 < nCh) {
                if (aload) pa = *(const float4*)(Ab + (c+1)*16);
                pb = bok ? *(const float4*)(Bb + (c+1)*16) : make_float4(0.f,0.f,0.f,0.f);
            }
            #pragma unroll
            for (int kk = 0; kk < 16; kk++) {
                float4 bv = *(const float4*)&Bs[cur + kk*SST + tx];
                float av[MR];
                if (MR == 4) {
                    float4 t = *(const float4*)&As[cur + kk*SST + ty];
                    av[0]=t.x; av[1]=t.y; av[2]=t.z; av[3]=t.w;
                } else {
                    float2 t = *(const float2*)&As[cur + kk*SST + ty];
                    av[0]=t.x; av[1]=t.y;
                }
                #pragma unroll
                for (int i = 0; i < MR; i++) {
                    acc[i][0]+=av[i]*bv.x; acc[i][1]+=av[i]*bv.y;
                    acc[i][2]+=av[i]*bv.z; acc[i][3]+=av[i]*bv.w;
                }
            }
            if (c + 1 < nCh) {
                int nb = ((c+1) & 1) * SBUF;
                if (aload) {
                    As[nb+(lk4+0)*SST+lrow]=pa.x; As[nb+(lk4+1)*SST+lrow]=pa.y;
                    As[nb+(lk4+2)*SST+lrow]=pa.z; As[nb+(lk4+3)*SST+lrow]=pa.w;
                }
                Bs[nb+(lk4+0)*SST+lrow]=pb.x; Bs[nb+(lk4+1)*SST+lrow]=pb.y;
                Bs[nb+(lk4+2)*SST+lrow]=pb.z; Bs[nb+(lk4+3)*SST+lrow]=pb.w;
            }
            __syncthreads();
        }

        size_t zoff = (splitK > 1) ? (size_t)z * NN * ldc : 0;
        #pragma unroll
        for (int i = 0; i < MR; i++) {
            int m = bm + ty + i;
            #pragma unroll
            for (int jj = 0; jj < 4; jj++) {
                int n = bn + tx + jj;
                if (n >= N) continue;
                float v = acc[i][jj];
                if (bias)      v += bias[n];
                if (flags & 1) v = fmaxf(v, 0.f);
                if (flags & 2) v += resid[(size_t)m*ldc + n];
                C[zoff + (size_t)m*ldc + n] = v;
            }
        }
        __syncthreads();
    }
}

// ---------------- Attention phase: KV in smem, 8 partials/token, 160 units ----------------
#define ATT_SK (NN*DHD + 4)
__device__ void dattn(float* sm) {
    float* sK = sm;
    float* sV = sm + ATT_SK;
    int tid = threadIdx.x;
    for (int u = blockIdx.x; u < NHEAD*16; u += GRID) {
        int h = u >> 4, chunk = u & 15;
        int bq = h*DHD, bk = DD + h*DHD, bv = 2*DD + h*DHD;
        for (int idx = tid; idx < NN*DHD; idx += NT) {
            int m = idx / DHD, c = idx - m*DHD;
            int sa = idx + (m >> 7);
            sK[sa] = g_qkv[m*3*DD + bk + c];
            sV[sa] = g_qkv[m*3*DD + bv + c];
        }
        __syncthreads();

        int token = chunk*32 + (tid >> 3);
        int p = tid & 7;
        const float scale = rsqrtf((float)DHD);
        float q[DHD];
        #pragma unroll
        for (int c = 0; c < DHD; c++) q[c] = g_qkv[token*3*DD + bq + c] * scale;

        float mx = -1e30f, l = 0.f, acc[DHD];
        #pragma unroll
        for (int c = 0; c < DHD; c++) acc[c] = 0.f;
        int mbase = p * 64;
        for (int i = 0; i < 64; i++) {
            int m = mbase + i;
            const float* kr = &sK[m*DHD + (m >> 7)];
            const float* vr = &sV[m*DHD + (m >> 7)];
            float s = q[0]*kr[0];
            #pragma unroll
            for (int c = 1; c < DHD; c++) s += q[c]*kr[c];
            if (s <= mx) {
                float e = __expf(s - mx);
                l += e;
                #pragma unroll
                for (int c = 0; c < DHD; c++) acc[c] += e*vr[c];
            } else {
                float corr = __expf(mx - s);
                l = l*corr + 1.f;
                #pragma unroll
                for (int c = 0; c < DHD; c++) acc[c] = acc[c]*corr + vr[c];
                mx = s;
            }
        }
        #pragma unroll
        for (int off = 1; off < 8; off <<= 1) {
            float om = __shfl_xor_sync(0xffffffffu, mx, off);
            float ol = __shfl_xor_sync(0xffffffffu, l, off);
            float nm = fmaxf(mx, om);
            float c1 = __expf(mx - nm), c2 = __expf(om - nm);
            l = l*c1 + ol*c2;
            #pragma unroll
            for (int c = 0; c < DHD; c++) {
                float oa = __shfl_xor_sync(0xffffffffu, acc[c], off);
                acc[c] = acc[c]*c1 + oa*c2;
            }
            mx = nm;
        }
        if (p == 0) {
            float rl = 1.f / l;
            #pragma unroll
            for (int c = 0; c < DHD; c++) g_att[token*DP + bq + c] = acc[c]*rl;
        }
        __syncthreads();
    }
}

// ---------------- LayerNorm phase: warp per row, x = LN(x + add(+bias)) ----------------
__device__ void dln(const float* __restrict__ add, int P, const float* __restrict__ bias,
                    const float* __restrict__ s, const float* __restrict__ b)
{
    int w = blockIdx.x * (NT/32) + (threadIdx.x >> 5);
    int lane = threadIdx.x & 31;
    if (w >= NN) return;
    float v[5];
    float s1 = 0.f, s2 = 0.f;
    #pragma unroll
    for (int i = 0; i < 5; i++) {
        int idx = lane + i*32;
        float xv = 0.f;
        if (idx < DD) {
            xv = g_x[w*DP + idx];
            if (bias) xv += bias[idx];
            for (int p = 0; p < P; p++) xv += add[(size_t)p*NN*DP + w*DP + idx];
        }
        v[i] = xv; s1 += xv; s2 += xv*xv;
    }
    #pragma unroll
    for (int o = 16; o; o >>= 1) {
        s1 += __shfl_xor_sync(0xffffffffu, s1, o);
        s2 += __shfl_xor_sync(0xffffffffu, s2, o);
    }
    float mean = s1 * (1.f/DD);
    float var  = s2 * (1.f/DD) - mean*mean;
    float rstd = rsqrtf(var + 1e-5f);
    #pragma unroll
    for (int i = 0; i < 5; i++) {
        int idx = lane + i*32;
        if (idx < DD) g_x[w*DP + idx] = (v[i] - mean)*rstd*s[idx] + b[idx];
    }
}

// ---------------- LSTM pointwise (after fused gates GEMM) ----------------
__device__ void dlstm_pt(const float* __restrict__ inp, int istride) {
    for (int e = blockIdx.x*NT + threadIdx.x; e < NN*HD; e += GRID*NT) {
        int n = e >> 7, j = e & 127;
        float in0 = inp[n*istride+0], in1 = inp[n*istride+1];
        float in2 = inp[n*istride+2], in3 = inp[n*istride+3];
        float g[4];
        #pragma unroll
        for (int gi = 0; gi < 4; gi++) {
            int row = gi*HD + j;
            g[gi] = g_gates[n*(4*HD) + row] + g_bcomb[row]
                  + g_Wcomb[row*4+0]*in0 + g_Wcomb[row*4+1]*in1
                  + g_Wcomb[row*4+2]*in2 + g_Wcomb[row*4+3]*in3;
        }
        float c2 = sigm(g[1])*g_c[e] + sigm(g[0])*tanhf(g[2]);
        g_c[e] = c2;
        g_x[n*DP + j] = sigm(g[3])*tanhf(c2);
        if (j < 2) g_x[n*DP + HD + j] = (j == 0) ? in0 : in1;
    }
}

// ---------------- Rollout head ----------------
__device__ void dhead(const float* __restrict__ W_pl, const float* __restrict__ b_pl,
                      const float* __restrict__ cf, int cfs, float* __restrict__ outp)
{
    int n = blockIdx.x*NT + threadIdx.x;
    if (n >= NN) return;
    const float* xr = g_mlp2 + n*HD;
    float a0 = b_pl[0], a1 = b_pl[1];
    #pragma unroll 4
    for (int k = 0; k < HD; k++) {
        a0 += xr[k]*W_pl[k];
        a1 += xr[k]*W_pl[HD+k];
    }
    const float* c = cf + n*cfs;
    const float DT = 0.1f;
    float v0 = a0*DT + c[2], v1 = a1*DT + c[3];
    float p0 = a0*(DT*DT*0.5f) + v0*DT + c[0];
    float p1 = a1*(DT*DT*0.5f) + v1*DT + c[1];
    outp[n*(PLEN*4)+0] = p0; outp[n*(PLEN*4)+1] = p1;
    outp[n*(PLEN*4)+2] = v0; outp[n*(PLEN*4)+3] = v1;
    g_inp[n*4+0] = p0; g_inp[n*4+1] = p1; g_inp[n*4+2] = v0; g_inp[n*4+3] = v1;
}

// ---------------- Setup phase 1: fold emb, zero state, repack weights ----------------
#define RP_ROWS (NLAY*3*DD + NLAY*DD + NLAY*FFD + HD)
__device__ void dsetup(const float* W_ih, const float* W_emb, const float* b_emb,
                       const float* b_ih, const float* b_hh,
                       const float* qkv_w, const float* out_w,
                       const float* ff1_w, const float* W_sp)
{
    int gtid = blockIdx.x*NT + threadIdx.x;
    const int nthr = GRID*NT;
    for (int j = gtid; j < 4*HD; j += nthr) {
        float wc0=0.f, wc1=0.f, wc2=0.f, wc3=0.f;
        float bb = b_ih[j] + b_hh[j];
        #pragma unroll 8
        for (int e = 0; e < ED; e++) {
            float w = W_ih[j*ED + e];
            bb  += w * b_emb[e];
            wc0 += w * W_emb[e*4 + 0];
            wc1 += w * W_emb[e*4 + 1];
            wc2 += w * W_emb[e*4 + 2];
            wc3 += w * W_emb[e*4 + 3];
        }
        g_Wcomb[j*4+0]=wc0; g_Wcomb[j*4+1]=wc1; g_Wcomb[j*4+2]=wc2; g_Wcomb[j*4+3]=wc3;
        g_bcomb[j]=bb;
    }
    for (int i = gtid; i < NN*HD; i += nthr) g_c[i] = 0.f;
    for (int i = gtid; i < NN*4*HD; i += nthr) g_gates[i] = 0.f;
    for (int i = gtid; i < NN*DP; i += nthr) { g_x[i] = 0.f; g_att[i] = 0.f; }
    for (int idx = gtid; idx < RP_ROWS*DP; idx += nthr) {
        int row = idx / DP, k = idx - row*DP;
        const float* src; float* dst; int r;
        if (row < NLAY*3*DD)                         { src = qkv_w; dst = g_qkvP; r = row; }
        else if (row < NLAY*3*DD+NLAY*DD)            { src = out_w; dst = g_outP; r = row - NLAY*3*DD; }
        else if (row < NLAY*3*DD+NLAY*DD+NLAY*FFD)   { src = ff1_w; dst = g_ff1P; r = row - NLAY*3*DD - NLAY*DD; }
        else                                         { src = W_sp;  dst = g_spP;  r = row - NLAY*3*DD - NLAY*DD - NLAY*FFD; }
        dst[r*DP + k] = (k < DD) ? src[r*DD + k] : 0.f;
    }
}

// ---------------- Setup phase 2: Wf = W_hh @ spP, bspW = W_hh @ b_sp ----------------
__device__ void dsetup2(const float* W_hh, const float* b_sp)
{
    int gtid = blockIdx.x*NT + threadIdx.x;
    const int nthr = GRID*NT;
    for (int idx = gtid; idx < 4*HD*DP; idx += nthr) {
        int row = idx / DP, d = idx - row*DP;
        float s = 0.f;
        #pragma unroll 8
        for (int r = 0; r < HD; r++) s += W_hh[row*HD + r] * g_spP[r*DP + d];
        g_Wf[idx] = s;
    }
    for (int row = gtid; row < 4*HD; row += nthr) {
        float s = 0.f;
        #pragma unroll 8
        for (int r = 0; r < HD; r++) s += W_hh[row*HD + r] * b_sp[r];
        g_bspW[row] = s;
    }
}

// ---------------- Encoder stack ----------------
__device__ void dsp(const float* qkv_b, const float* out_b, const float* ff1_b,
                    const float* ff2_w, const float* ff2_b,
                    const float* ln1_s, const float* ln1_b,
                    const float* ln2_s, const float* ln2_b,
                    const float* b_sp, bool emitSh, float* sm)
{
    for (int j = 0; j < NLAY; j++) {
        dgemm_t<32>(g_x, g_qkvP + (size_t)j*3*DD*DP, qkv_b + j*3*DD, nullptr, g_qkv,
                    3*DD, DP, DP, 3*DD, DP, 1, 0, sm);
        gridbar();
        dattn(sm);
        gridbar();
        dgemm_t<32>(g_att, g_outP + (size_t)j*DD*DP, out_b + j*DD, nullptr, g_tmp,
                    DD, DP, DP, DP, DP, 1, 0, sm);
        gridbar();
        dln(g_tmp, 1, nullptr, ln1_s + j*DD, ln1_b + j*DD);
        gridbar();
        dgemm_t<64>(g_x, g_ff1P + (size_t)j*FFD*DP, ff1_b + j*FFD, nullptr, g_ff1,
                    FFD, DP, DP, FFD, DP, 1, 1, sm);
        gridbar();
        dgemm_t<64>(g_ff1, ff2_w + (size_t)j*DD*FFD, nullptr, nullptr, g_part,
                    DD, FFD, FFD, DP, FFD, 8, 0, sm);
        gridbar();
        dln(g_part, 8, ff2_b + j*DD, ln2_s + j*DD, ln2_b + j*DD);
        gridbar();
    }
    if (emitSh) {
        dgemm_t<32>(g_x, g_spP, b_sp, nullptr, g_Sh, HD, DP, DP, HD, DP, 1, 0, sm);
        gridbar();
    }
}

// ---------------- Megakernel ----------------
__global__ void __launch_bounds__(NT, 2) mega(
    const float* Tracks, const float* W_emb, const float* b_emb,
    const float* W_ih, const float* W_hh, const float* b_ih, const float* b_hh,
    const float* qkv_w, const float* qkv_b, const float* out_w, const float* out_b,
    const float* ff1_w, const float* ff1_b, const float* ff2_w, const float* ff2_b,
    const float* ln1_s, const float* ln1_b, const float* ln2_s, const float* ln2_b,
    const float* W_sp, const float* b_sp, const float* W_p1, const float* b_p1,
    const float* W_p2, const float* b_p2, const float* W_pl, const float* b_pl,
    float* out)
{
    extern __shared__ float sm[];
    dsetup(W_ih, W_emb, b_emb, b_ih, b_hh, qkv_w, out_w, ff1_w, W_sp);
    gridbar();
    dsetup2(W_hh, b_sp);
    gridbar();

    // History: t=-1 uses Tracks[:,0,1:] with zero carry (g_gates zeroed in setup)
    for (int t = -1; t < LHIST; t++) {
        const float* ib = (t < 0) ? (Tracks + 1) : (Tracks + t*5 + 1);
        if (t >= 0) {
            // fused gates: gates = x_prev @ Wf^T + W_hh@b_sp  (== W_hh @ Sh_prev)
            dgemm_t<32>(g_x, g_Wf, g_bspW, nullptr, g_gates,
                        4*HD, DP, DP, 4*HD, DP, 1, 0, sm);
            gridbar();
        }
        dlstm_pt(ib, LHIST*5);
        gridbar();
        dsp(qkv_b, out_b, ff1_b, ff2_w, ff2_b, ln1_s, ln1_b, ln2_s, ln2_b, b_sp,
            /*emitSh=*/(t == LHIST-1), sm);
    }
    // Rollout
    for (int t = 0; t < PLEN; t++) {
        dgemm_t<32>(g_Sh, W_p1, b_p1, g_Sh, g_mlp1, HD, HD, HD, HD, HD, 1, 3, sm);
        gridbar();
        dgemm_t<32>(g_mlp1, W_p2, b_p2, g_mlp1, g_mlp2, HD, HD, HD, HD, HD, 1, 3, sm);
        gridbar();
        dhead(W_pl, b_pl, (t == 0) ? (Tracks + (LHIST-1)*5 + 1) : g_inp,
              (t == 0) ? LHIST*5 : 4, out + t*4);
        gridbar();
        if (t < PLEN - 1) {     // last rm_sp's carry is discarded by the scan
            dgemm_t<32>(g_x, g_Wf, g_bspW, nullptr, g_gates,
                        4*HD, DP, DP, 4*HD, DP, 1, 0, sm);
            gridbar();
            dlstm_pt(g_inp, 4);
            gridbar();
            dsp(qkv_b, out_b, ff1_b, ff2_w, ff2_b, ln1_s, ln1_b, ln2_s, ln2_b, b_sp,
                /*emitSh=*/true, sm);
        }
    }
}

// ---------------- Host ----------------
extern "C" void kernel_launch(void* const* d_in, const int* in_sizes, int n_in,
                              void* d_out, int out_size) {
    const float* Tracks = (const float*)d_in[0];
    const float* W_emb  = (const float*)d_in[1];
    const float* b_emb  = (const float*)d_in[2];
    const float* W_ih   = (const float*)d_in[3];
    const float* W_hh   = (const float*)d_in[4];
    const float* b_ih   = (const float*)d_in[5];
    const float* b_hh   = (const float*)d_in[6];
    const float* qkv_w  = (const float*)d_in[7];
    const float* qkv_b  = (const float*)d_in[8];
    const float* out_w  = (const float*)d_in[9];
    const float* out_b  = (const float*)d_in[10];
    const float* ff1_w  = (const float*)d_in[11];
    const float* ff1_b  = (const float*)d_in[12];
    const float* ff2_w  = (const float*)d_in[13];
    const float* ff2_b  = (const float*)d_in[14];
    const float* ln1_s  = (const float*)d_in[15];
    const float* ln1_b  = (const float*)d_in[16];
    const float* ln2_s  = (const float*)d_in[17];
    const float* ln2_b  = (const float*)d_in[18];
    const float* W_sp   = (const float*)d_in[19];
    const float* b_sp   = (const float*)d_in[20];
    const float* W_p1   = (const float*)d_in[21];
    const float* b_p1   = (const float*)d_in[22];
    const float* W_p2   = (const float*)d_in[23];
    const float* b_p2   = (const float*)d_in[24];
    const float* W_pl   = (const float*)d_in[25];
    const float* b_pl   = (const float*)d_in[26];
    float* out = (float*)d_out;

    // smem = max(attention KV: 2*(512*13+4)*4 = 53280B, gemm: 4*16*68*4 = 17408B)
    const int SMEM = 2*ATT_SK*(int)sizeof(float);
    static int configured = 0;
    if (!configured) {
        cudaFuncSetAttribute(mega, cudaFuncAttributeMaxDynamicSharedMemorySize, SMEM);
        configured = 1;
    }

    mega<<<GRID, NT, SMEM>>>(Tracks, W_emb, b_emb, W_ih, W_hh, b_ih, b_hh,
                             qkv_w, qkv_b, out_w, out_b, ff1_w, ff1_b, ff2_w, ff2_b,
                             ln1_s, ln1_b, ln2_s, ln2_b, W_sp, b_sp,
                             W_p1, b_p1, W_p2, b_p2, W_pl, b_pl, out);
}